// round 14
// baseline (speedup 1.0000x reference)
#include <cuda_runtime.h>
#include <cstdint>

#define S_  16
#define T_  400
#define F_  16
#define SF_ 250
#define G_  4
#define H1  32
#define H2  16

#define THREADS  256
#define R_       2
#define CHUNKS   9
#define ROWS_S   (T_ * (SF_ + 1))                    // 100400
#define ROWS_CTA ((ROWS_S + CHUNKS - 1) / CHUNKS)    // 11156

// P-table: [cp 0..15][g 0..3][t 0..399] of 8-byte f32 pairs (c = 2cp, 2cp+1)
#define PLANE_B   3200                    // 400 * 8 bytes (one (cp,g) plane)
#define CP_STRIDE 12800                   // 4 * PLANE_B
#define P_BYTES   (16 * CP_STRIDE)        // 204800
// smem layout (bytes): P | W1[2048] | W2[2048] | B1[128] | B2[64] | W3[64]
#define OFF_W1  P_BYTES
#define OFF_W2  (OFF_W1 + 2048)
#define OFF_B1  (OFF_W2 + 2048)
#define OFF_B2  (OFF_B1 + 128)
#define OFF_W3  (OFF_B2 + 64)
#define SMEM_BYTES (OFF_W3 + 64)          // 209,152

typedef unsigned long long ull;

__device__ __forceinline__ ull pk2(float a, float b) {
    ull r; asm("mov.b64 %0, {%1,%2};" : "=l"(r) : "f"(a), "f"(b)); return r;
}
__device__ __forceinline__ void upk(ull p, float& a, float& b) {
    asm("mov.b64 {%0,%1}, %2;" : "=f"(a), "=f"(b) : "l"(p));
}
__device__ __forceinline__ ull fma2(ull a, ull b, ull c) {
    ull d; asm("fma.rn.f32x2 %0, %1, %2, %3;" : "=l"(d) : "l"(a), "l"(b), "l"(c)); return d;
}
__device__ __forceinline__ ull add2(ull a, ull b) {
    ull d; asm("add.rn.f32x2 %0, %1, %2;" : "=l"(d) : "l"(a), "l"(b)); return d;
}
__device__ __forceinline__ ull mul2(ull a, ull b) {
    ull d; asm("mul.rn.f32x2 %0, %1, %2;" : "=l"(d) : "l"(a), "l"(b)); return d;
}
// packed leaky-relu: lrelu(x) = 0.505x + 0.495|x|
__device__ __forceinline__ ull lrelu2(ull x, ull c505, ull c495) {
    ull ax = x & 0x7FFFFFFF7FFFFFFFull;
    return fma2(ax, c495, mul2(x, c505));
}
__device__ __forceinline__ float lrelu(float x) { return fmaxf(x, 0.01f * x); }

struct RowIdx { int off[G_]; };   // byte offset within each g's set of planes

__device__ __forceinline__ RowIdx load_idx(const int* __restrict__ perm, int s, int idx) {
    RowIdx r;
    int sfp = idx / T_;
    int t   = idx - sfp * T_;
    if (sfp == 0) {
        r.off[0] = t * 8;
        r.off[1] = PLANE_B + t * 8;
        r.off[2] = 2 * PLANE_B + t * 8;
        r.off[3] = 3 * PLANE_B + t * 8;
    } else {
        int base = ((sfp - 1) * (G_ * S_) + s) * T_ + t;
        r.off[0] = perm[base] * 8;
        r.off[1] = PLANE_B + perm[base + S_ * T_] * 8;
        r.off[2] = 2 * PLANE_B + perm[base + 2 * S_ * T_] * 8;
        r.off[3] = 3 * PLANE_B + perm[base + 3 * S_ * T_] * 8;
    }
    return r;
}

__global__ __launch_bounds__(THREADS, 1)
void fused_kernel(const float* __restrict__ obs,
                  const float* __restrict__ mu,
                  const float* __restrict__ Sig,
                  const int*   __restrict__ perm,
                  const float* __restrict__ W1,
                  const float* __restrict__ b1,
                  const float* __restrict__ W2,
                  const float* __restrict__ b2,
                  const float* __restrict__ W3,
                  const float* __restrict__ b3,
                  float* __restrict__ out) {
    extern __shared__ __align__(16) char sm[];
    float* sW1 = (float*)(sm + OFF_W1);   // [j][c] stride 32
    float* sW2 = (float*)(sm + OFF_W2);   // [i][j] stride 16
    float* sB1 = (float*)(sm + OFF_B1);
    float* sB2 = (float*)(sm + OFF_B2);
    float* sW3 = (float*)(sm + OFF_W3);

    const int s   = blockIdx.y;
    const int k   = blockIdx.x;
    const int tid = threadIdx.x;

    // ---- W1eff = Sigma^T W1 (normalize folded into layer 1) ----
    for (int m = tid; m < F_ * H1; m += THREADS) {
        int j = m >> 5, c = m & 31;
        float acc = 0.f;
        #pragma unroll
        for (int i = 0; i < F_; i++) acc += Sig[i * F_ + j] * W1[i * H1 + c];
        sW1[j * H1 + c] = acc;
    }
    // ---- b1eff = b1 - mu^T W1eff ----
    if (tid < H1) {
        int c = tid;
        float bacc = 0.f;
        #pragma unroll
        for (int j = 0; j < F_; j++) {
            float wj = 0.f;
            #pragma unroll
            for (int i = 0; i < F_; i++) wj += Sig[i * F_ + j] * W1[i * H1 + c];
            bacc += mu[j] * wj;
        }
        sB1[c] = b1[c] - bacc;
    }
    for (int m = tid; m < H1 * H2; m += THREADS) sW2[m] = W2[m];
    if (tid < H2) sB2[tid] = b2[tid];
    if (tid < H2) sW3[tid] = W3[tid];
    __syncthreads();

    // ---- build P table: P[cp][g][t] = pair of dot(obs[s,t,4g:4g+4], W1eff[4g:, 2cp..2cp+1])
    //      b1eff folded into the g==0 planes ----
    const float* obsS = obs + s * (T_ * F_);
    for (int it = tid; it < G_ * T_; it += THREADS) {
        int g = it / T_, t = it - g * T_;
        float4 x = *(const float4*)(obsS + t * F_ + g * 4);
        ull xx = pk2(x.x, x.x), xy = pk2(x.y, x.y);
        ull xz = pk2(x.z, x.z), xw = pk2(x.w, x.w);
        const char* wrow = (const char*)sW1 + g * 4 * 128;   // row j = 4g
        char* dst = sm + g * PLANE_B + t * 8;
        const ull* bp = (const ull*)sB1;
        #pragma unroll
        for (int cp = 0; cp < 16; cp++) {
            ull acc = (g == 0) ? bp[cp] : 0ULL;
            acc = fma2(xx, *(const ull*)(wrow + cp * 8), acc);
            acc = fma2(xy, *(const ull*)(wrow + 128 + cp * 8), acc);
            acc = fma2(xz, *(const ull*)(wrow + 256 + cp * 8), acc);
            acc = fma2(xw, *(const ull*)(wrow + 384 + cp * 8), acc);
            *(ull*)(dst + cp * CP_STRIDE) = acc;
        }
    }
    __syncthreads();

    const float b3v = b3[0];
    const int rowsBeg = k * ROWS_CTA;
    const int rowsEnd = (rowsBeg + ROWS_CTA < ROWS_S) ? rowsBeg + ROWS_CTA : ROWS_S;
    float* outS = out + s * ROWS_S;

    const ull c505 = pk2(0.505f, 0.505f);
    const ull c495 = pk2(0.495f, 0.495f);

    int idx0 = rowsBeg + tid;
    if (idx0 >= rowsEnd) return;

    RowIdx ra[R_];
    #pragma unroll
    for (int r = 0; r < R_; r++) {
        int id = idx0 + r * THREADS;
        ra[r] = load_idx(perm, s, id < rowsEnd ? id : rowsEnd - 1);
    }

    while (true) {
        const int curBase = idx0;
        RowIdx ci[R_];
        #pragma unroll
        for (int r = 0; r < R_; r++) ci[r] = ra[r];

        // ---- prefetch next iteration's perm indices ----
        idx0 += R_ * THREADS;
        const bool more = (idx0 < rowsEnd);
        if (more) {
            #pragma unroll
            for (int r = 0; r < R_; r++) {
                int id = idx0 + r * THREADS;
                ra[r] = load_idx(perm, s, id < rowsEnd ? id : rowsEnd - 1);
            }
        }

        // ---- layer 1 via P-table gather: h[r][cp] = sum_g P[cp][g][t_rg] ----
        ull h[R_][16];
        #pragma unroll
        for (int cp = 0; cp < 16; cp++) {
            #pragma unroll
            for (int r = 0; r < R_; r++) {
                ull v0 = *(const ull*)(sm + ci[r].off[0] + cp * CP_STRIDE);
                ull v1 = *(const ull*)(sm + ci[r].off[1] + cp * CP_STRIDE);
                ull v2 = *(const ull*)(sm + ci[r].off[2] + cp * CP_STRIDE);
                ull v3 = *(const ull*)(sm + ci[r].off[3] + cp * CP_STRIDE);
                h[r][cp] = add2(add2(v0, v1), add2(v2, v3));
            }
        }

        // ---- layer-2 accumulators (init with b2) ----
        ull c2[R_][8];
        {
            const ull* pb = (const ull*)sB2;
            #pragma unroll
            for (int r = 0; r < R_; r++)
                #pragma unroll
                for (int p = 0; p < 8; p++) c2[r][p] = pb[p];
        }

        // ---- packed lrelu + layer 2 ----
        #pragma unroll
        for (int cp = 0; cp < 16; cp++) {
            const ulonglong2* wu = (const ulonglong2*)(sW2 + (2 * cp) * H2);
            const ulonglong2* wv = (const ulonglong2*)(sW2 + (2 * cp + 1) * H2);
            ulonglong2 u0 = wu[0], u1 = wu[1], u2 = wu[2], u3 = wu[3];
            ulonglong2 v0 = wv[0], v1 = wv[1], v2 = wv[2], v3 = wv[3];
            #pragma unroll
            for (int r = 0; r < R_; r++) {
                ull lr = lrelu2(h[r][cp], c505, c495);
                float au, av;
                upk(lr, au, av);
                ull au2 = pk2(au, au), av2 = pk2(av, av);
                c2[r][0] = fma2(au2, u0.x, c2[r][0]);
                c2[r][1] = fma2(au2, u0.y, c2[r][1]);
                c2[r][2] = fma2(au2, u1.x, c2[r][2]);
                c2[r][3] = fma2(au2, u1.y, c2[r][3]);
                c2[r][4] = fma2(au2, u2.x, c2[r][4]);
                c2[r][5] = fma2(au2, u2.y, c2[r][5]);
                c2[r][6] = fma2(au2, u3.x, c2[r][6]);
                c2[r][7] = fma2(au2, u3.y, c2[r][7]);
                c2[r][0] = fma2(av2, v0.x, c2[r][0]);
                c2[r][1] = fma2(av2, v0.y, c2[r][1]);
                c2[r][2] = fma2(av2, v1.x, c2[r][2]);
                c2[r][3] = fma2(av2, v1.y, c2[r][3]);
                c2[r][4] = fma2(av2, v2.x, c2[r][4]);
                c2[r][5] = fma2(av2, v2.y, c2[r][5]);
                c2[r][6] = fma2(av2, v3.x, c2[r][6]);
                c2[r][7] = fma2(av2, v3.y, c2[r][7]);
            }
        }

        // ---- layer 3 (packed) + sigmoid + guarded store ----
        const ull* w3p = (const ull*)sW3;
        #pragma unroll
        for (int r = 0; r < R_; r++) {
            ull zp = 0;
            #pragma unroll
            for (int p = 0; p < 8; p++) {
                ull lr = lrelu2(c2[r][p], c505, c495);
                zp = fma2(lr, w3p[p], zp);
            }
            float z0, z1;
            upk(zp, z0, z1);
            float z = b3v + z0 + z1;
            int cid = curBase + r * THREADS;
            if (cid < rowsEnd) outS[cid] = 1.f / (1.f + __expf(-z));
        }

        if (!more) break;
    }
}

extern "C" void kernel_launch(void* const* d_in, const int* in_sizes, int n_in,
                              void* d_out, int out_size) {
    const float* obs  = (const float*)d_in[0];
    const float* mu   = (const float*)d_in[1];
    const float* Sig  = (const float*)d_in[2];
    const int*   perm = (const int*)d_in[3];
    const float* W1   = (const float*)d_in[4];
    const float* b1   = (const float*)d_in[5];
    const float* W2   = (const float*)d_in[6];
    const float* b2   = (const float*)d_in[7];
    const float* W3   = (const float*)d_in[8];
    const float* b3   = (const float*)d_in[9];
    float* out = (float*)d_out;

    cudaFuncSetAttribute(fused_kernel, cudaFuncAttributeMaxDynamicSharedMemorySize, SMEM_BYTES);

    dim3 grid(CHUNKS, S_);
    fused_kernel<<<grid, THREADS, SMEM_BYTES>>>(obs, mu, Sig, perm, W1, b1, W2, b2, W3, b3, out);
}

// round 15
// speedup vs baseline: 1.4468x; 1.4468x over previous
#include <cuda_runtime.h>
#include <cstdint>

#define S_  16
#define T_  400
#define F_  16
#define SF_ 250
#define G_  4
#define H1  32
#define H2  16

#define THREADS  256
#define R_       4
#define CHUNKS   9
#define ROWS_S   (T_ * (SF_ + 1))                    // 100400
#define ROWS_CTA ((ROWS_S + CHUNKS - 1) / CHUNKS)    // 11156

// P-table: 1600 rows (rowid = g*400+t), each 32 fp16 c-values (64 B) in an
// 80-B stride slot -> 16B chunk start-slot = (5t+q) mod 8, uniform.
#define P_STRIDE 80
#define P_BYTES  (G_ * T_ * P_STRIDE)                // 128000
#define OFF_W1   P_BYTES                              // f32 W1eff [j][c], 2048 B
#define OFF_W2   (OFF_W1 + 2048)                      // f32 W2 [i][j], 2048 B
#define OFF_B1   (OFF_W2 + 2048)                      // f32 b1eff, 128 B
#define OFF_B2   (OFF_B1 + 128)                       // f32 b2, 64 B
#define OFF_W3   (OFF_B2 + 64)                        // f32 W3, 64 B
#define SMEM_BYTES (OFF_W3 + 64)                      // 132,368 B

typedef unsigned long long ull;
typedef unsigned int u32;

__device__ __forceinline__ ull pk2(float a, float b) {
    ull r; asm("mov.b64 %0, {%1,%2};" : "=l"(r) : "f"(a), "f"(b)); return r;
}
__device__ __forceinline__ void upk(ull p, float& a, float& b) {
    asm("mov.b64 {%0,%1}, %2;" : "=f"(a), "=f"(b) : "l"(p));
}
__device__ __forceinline__ ull fma2(ull a, ull b, ull c) {
    ull d; asm("fma.rn.f32x2 %0, %1, %2, %3;" : "=l"(d) : "l"(a), "l"(b), "l"(c)); return d;
}
__device__ __forceinline__ ull mul2(ull a, ull b) {
    ull d; asm("mul.rn.f32x2 %0, %1, %2;" : "=l"(d) : "l"(a), "l"(b)); return d;
}
__device__ __forceinline__ u32 hadd2(u32 a, u32 b) {
    u32 d; asm("add.rn.f16x2 %0, %1, %2;" : "=r"(d) : "r"(a), "r"(b)); return d;
}
// pack two f32 into fp16x2 (x0 -> low half)
__device__ __forceinline__ u32 f2h2(float x0, float x1) {
    u32 r; asm("cvt.rn.f16x2.f32 %0, %1, %2;" : "=r"(r) : "f"(x1), "f"(x0)); return r;
}
// unpack fp16x2 -> two f32 (low half -> a)
__device__ __forceinline__ void h2f2(u32 h, float& a, float& b) {
    unsigned short lo = (unsigned short)(h & 0xFFFF);
    unsigned short hi = (unsigned short)(h >> 16);
    asm("cvt.f32.f16 %0, %1;" : "=f"(a) : "h"(lo));
    asm("cvt.f32.f16 %0, %1;" : "=f"(b) : "h"(hi));
}
// packed leaky-relu on f32x2: lrelu(x) = 0.505x + 0.495|x|
__device__ __forceinline__ ull lrelu2(ull x, ull c505, ull c495) {
    ull ax = x & 0x7FFFFFFF7FFFFFFFull;
    return fma2(ax, c495, mul2(x, c505));
}
__device__ __forceinline__ float lrelu(float x) { return fmaxf(x, 0.01f * x); }

struct RowIdx { int off[G_]; };   // byte offsets of P rows (rowid * P_STRIDE)

__device__ __forceinline__ RowIdx load_idx(const int* __restrict__ perm, int s, int idx) {
    RowIdx r;
    int sfp = idx / T_;
    int t   = idx - sfp * T_;
    if (sfp == 0) {
        r.off[0] = t * P_STRIDE;
        r.off[1] = (T_ + t) * P_STRIDE;
        r.off[2] = (2 * T_ + t) * P_STRIDE;
        r.off[3] = (3 * T_ + t) * P_STRIDE;
    } else {
        int base = ((sfp - 1) * (G_ * S_) + s) * T_ + t;
        r.off[0] = perm[base] * P_STRIDE;
        r.off[1] = (T_ + perm[base + S_ * T_]) * P_STRIDE;
        r.off[2] = (2 * T_ + perm[base + 2 * S_ * T_]) * P_STRIDE;
        r.off[3] = (3 * T_ + perm[base + 3 * S_ * T_]) * P_STRIDE;
    }
    return r;
}

__global__ __launch_bounds__(THREADS, 1)
void fused_kernel(const float* __restrict__ obs,
                  const float* __restrict__ mu,
                  const float* __restrict__ Sig,
                  const int*   __restrict__ perm,
                  const float* __restrict__ W1,
                  const float* __restrict__ b1,
                  const float* __restrict__ W2,
                  const float* __restrict__ b2,
                  const float* __restrict__ W3,
                  const float* __restrict__ b3,
                  float* __restrict__ out) {
    extern __shared__ __align__(16) char sm[];
    float* sW1 = (float*)(sm + OFF_W1);   // [j][c] stride 32
    float* sW2 = (float*)(sm + OFF_W2);   // [i][j] stride 16
    float* sB1 = (float*)(sm + OFF_B1);
    float* sB2 = (float*)(sm + OFF_B2);
    float* sW3 = (float*)(sm + OFF_W3);

    const int s   = blockIdx.y;
    const int k   = blockIdx.x;
    const int tid = threadIdx.x;

    // ---- W1eff = Sigma^T W1 (normalize folded into layer 1) ----
    for (int m = tid; m < F_ * H1; m += THREADS) {
        int j = m >> 5, c = m & 31;
        float acc = 0.f;
        #pragma unroll
        for (int i = 0; i < F_; i++) acc += Sig[i * F_ + j] * W1[i * H1 + c];
        sW1[j * H1 + c] = acc;
    }
    // ---- b1eff = b1 - mu^T W1eff ----
    if (tid < H1) {
        int c = tid;
        float bacc = 0.f;
        #pragma unroll
        for (int j = 0; j < F_; j++) {
            float wj = 0.f;
            #pragma unroll
            for (int i = 0; i < F_; i++) wj += Sig[i * F_ + j] * W1[i * H1 + c];
            bacc += mu[j] * wj;
        }
        sB1[c] = b1[c] - bacc;
    }
    for (int m = tid; m < H1 * H2; m += THREADS) sW2[m] = W2[m];
    if (tid < H2) sB2[tid] = b2[tid];
    if (tid < H2) sW3[tid] = W3[tid];
    __syncthreads();

    // ---- build fp16 P table: row (g,t) = 32 c of dot(obs[s,t,4g:4g+4], W1eff[4g:,c])
    //      (b1eff folded into g==0 rows) ----
    const float* obsS = obs + s * (T_ * F_);
    for (int it = tid; it < G_ * T_; it += THREADS) {
        int g = it / T_, t = it - g * T_;
        float4 x = *(const float4*)(obsS + t * F_ + g * 4);
        ull xx = pk2(x.x, x.x), xy = pk2(x.y, x.y);
        ull xz = pk2(x.z, x.z), xw = pk2(x.w, x.w);
        const char* wrow = (const char*)sW1 + g * 4 * 128;   // rows j=4g..4g+3
        const ull* bp = (const ull*)sB1;
        u32 hp[16];
        #pragma unroll
        for (int cp = 0; cp < 16; cp++) {
            ull acc = (g == 0) ? bp[cp] : 0ULL;
            acc = fma2(xx, *(const ull*)(wrow + cp * 8), acc);
            acc = fma2(xy, *(const ull*)(wrow + 128 + cp * 8), acc);
            acc = fma2(xz, *(const ull*)(wrow + 256 + cp * 8), acc);
            acc = fma2(xw, *(const ull*)(wrow + 384 + cp * 8), acc);
            float a, b;
            upk(acc, a, b);
            hp[cp] = f2h2(a, b);
        }
        char* dst = sm + it * P_STRIDE;
        #pragma unroll
        for (int q = 0; q < 4; q++)
            *(uint4*)(dst + q * 16) = make_uint4(hp[4 * q], hp[4 * q + 1],
                                                 hp[4 * q + 2], hp[4 * q + 3]);
    }
    __syncthreads();

    const float b3v = b3[0];
    const int rowsBeg = k * ROWS_CTA;
    const int rowsEnd = (rowsBeg + ROWS_CTA < ROWS_S) ? rowsBeg + ROWS_CTA : ROWS_S;
    float* outS = out + s * ROWS_S;

    const ull c505 = pk2(0.505f, 0.505f);
    const ull c495 = pk2(0.495f, 0.495f);

    int idx0 = rowsBeg + tid;
    if (idx0 >= rowsEnd) return;

    RowIdx ra[R_];
    #pragma unroll
    for (int r = 0; r < R_; r++) {
        int id = idx0 + r * THREADS;
        ra[r] = load_idx(perm, s, id < rowsEnd ? id : rowsEnd - 1);
    }

    while (true) {
        const int curBase = idx0;
        RowIdx ci[R_];
        #pragma unroll
        for (int r = 0; r < R_; r++) ci[r] = ra[r];

        // ---- prefetch next iteration's perm indices ----
        idx0 += R_ * THREADS;
        const bool more = (idx0 < rowsEnd);
        if (more) {
            #pragma unroll
            for (int r = 0; r < R_; r++) {
                int id = idx0 + r * THREADS;
                ra[r] = load_idx(perm, s, id < rowsEnd ? id : rowsEnd - 1);
            }
        }

        // ---- layer 1: gather 4 fp16 P rows per output row, HADD2 tree ----
        u32 h[R_][16];   // fp16x2 pairs
        #pragma unroll
        for (int r = 0; r < R_; r++) {
            uint4 a0 = *(const uint4*)(sm + ci[r].off[0]);
            uint4 a1 = *(const uint4*)(sm + ci[r].off[0] + 16);
            uint4 a2 = *(const uint4*)(sm + ci[r].off[0] + 32);
            uint4 a3 = *(const uint4*)(sm + ci[r].off[0] + 48);
            uint4 b0 = *(const uint4*)(sm + ci[r].off[1]);
            uint4 b1q = *(const uint4*)(sm + ci[r].off[1] + 16);
            uint4 b2q = *(const uint4*)(sm + ci[r].off[1] + 32);
            uint4 b3q = *(const uint4*)(sm + ci[r].off[1] + 48);
            uint4 c0 = *(const uint4*)(sm + ci[r].off[2]);
            uint4 c1 = *(const uint4*)(sm + ci[r].off[2] + 16);
            uint4 c2q = *(const uint4*)(sm + ci[r].off[2] + 32);
            uint4 c3 = *(const uint4*)(sm + ci[r].off[2] + 48);
            uint4 d0 = *(const uint4*)(sm + ci[r].off[3]);
            uint4 d1 = *(const uint4*)(sm + ci[r].off[3] + 16);
            uint4 d2 = *(const uint4*)(sm + ci[r].off[3] + 32);
            uint4 d3 = *(const uint4*)(sm + ci[r].off[3] + 48);
            // sum the four g-rows pairwise
            h[r][0]  = hadd2(hadd2(a0.x, b0.x),  hadd2(c0.x, d0.x));
            h[r][1]  = hadd2(hadd2(a0.y, b0.y),  hadd2(c0.y, d0.y));
            h[r][2]  = hadd2(hadd2(a0.z, b0.z),  hadd2(c0.z, d0.z));
            h[r][3]  = hadd2(hadd2(a0.w, b0.w),  hadd2(c0.w, d0.w));
            h[r][4]  = hadd2(hadd2(a1.x, b1q.x), hadd2(c1.x, d1.x));
            h[r][5]  = hadd2(hadd2(a1.y, b1q.y), hadd2(c1.y, d1.y));
            h[r][6]  = hadd2(hadd2(a1.z, b1q.z), hadd2(c1.z, d1.z));
            h[r][7]  = hadd2(hadd2(a1.w, b1q.w), hadd2(c1.w, d1.w));
            h[r][8]  = hadd2(hadd2(a2.x, b2q.x), hadd2(c2q.x, d2.x));
            h[r][9]  = hadd2(hadd2(a2.y, b2q.y), hadd2(c2q.y, d2.y));
            h[r][10] = hadd2(hadd2(a2.z, b2q.z), hadd2(c2q.z, d2.z));
            h[r][11] = hadd2(hadd2(a2.w, b2q.w), hadd2(c2q.w, d2.w));
            h[r][12] = hadd2(hadd2(a3.x, b3q.x), hadd2(c3.x, d3.x));
            h[r][13] = hadd2(hadd2(a3.y, b3q.y), hadd2(c3.y, d3.y));
            h[r][14] = hadd2(hadd2(a3.z, b3q.z), hadd2(c3.z, d3.z));
            h[r][15] = hadd2(hadd2(a3.w, b3q.w), hadd2(c3.w, d3.w));
        }

        // ---- layer-2 accumulators (init with b2) ----
        ull c2[R_][8];
        {
            const ull* pb = (const ull*)sB2;
            #pragma unroll
            for (int r = 0; r < R_; r++)
                #pragma unroll
                for (int p = 0; p < 8; p++) c2[r][p] = pb[p];
        }

        // ---- lrelu + layer 2 (per c-pair) ----
        #pragma unroll
        for (int cp = 0; cp < 16; cp++) {
            const ulonglong2* wu = (const ulonglong2*)(sW2 + (2 * cp) * H2);
            const ulonglong2* wv = (const ulonglong2*)(sW2 + (2 * cp + 1) * H2);
            ulonglong2 u0 = wu[0], u1 = wu[1], u2 = wu[2], u3 = wu[3];
            ulonglong2 v0 = wv[0], v1 = wv[1], v2 = wv[2], v3 = wv[3];
            #pragma unroll
            for (int r = 0; r < R_; r++) {
                float fa, fb;
                h2f2(h[r][cp], fa, fb);
                float au = lrelu(fa), av = lrelu(fb);
                ull au2 = pk2(au, au), av2 = pk2(av, av);
                c2[r][0] = fma2(au2, u0.x, c2[r][0]);
                c2[r][1] = fma2(au2, u0.y, c2[r][1]);
                c2[r][2] = fma2(au2, u1.x, c2[r][2]);
                c2[r][3] = fma2(au2, u1.y, c2[r][3]);
                c2[r][4] = fma2(au2, u2.x, c2[r][4]);
                c2[r][5] = fma2(au2, u2.y, c2[r][5]);
                c2[r][6] = fma2(au2, u3.x, c2[r][6]);
                c2[r][7] = fma2(au2, u3.y, c2[r][7]);
                c2[r][0] = fma2(av2, v0.x, c2[r][0]);
                c2[r][1] = fma2(av2, v0.y, c2[r][1]);
                c2[r][2] = fma2(av2, v1.x, c2[r][2]);
                c2[r][3] = fma2(av2, v1.y, c2[r][3]);
                c2[r][4] = fma2(av2, v2.x, c2[r][4]);
                c2[r][5] = fma2(av2, v2.y, c2[r][5]);
                c2[r][6] = fma2(av2, v3.x, c2[r][6]);
                c2[r][7] = fma2(av2, v3.y, c2[r][7]);
            }
        }

        // ---- layer 3 (packed) + sigmoid + guarded store ----
        const ull* w3p = (const ull*)sW3;
        #pragma unroll
        for (int r = 0; r < R_; r++) {
            ull zp = 0;
            #pragma unroll
            for (int p = 0; p < 8; p++) {
                ull lr = lrelu2(c2[r][p], c505, c495);
                zp = fma2(lr, w3p[p], zp);
            }
            float z0, z1;
            upk(zp, z0, z1);
            float z = b3v + z0 + z1;
            int cid = curBase + r * THREADS;
            if (cid < rowsEnd) outS[cid] = 1.f / (1.f + __expf(-z));
        }

        if (!more) break;
    }
}

extern "C" void kernel_launch(void* const* d_in, const int* in_sizes, int n_in,
                              void* d_out, int out_size) {
    const float* obs  = (const float*)d_in[0];
    const float* mu   = (const float*)d_in[1];
    const float* Sig  = (const float*)d_in[2];
    const int*   perm = (const int*)d_in[3];
    const float* W1   = (const float*)d_in[4];
    const float* b1   = (const float*)d_in[5];
    const float* W2   = (const float*)d_in[6];
    const float* b2   = (const float*)d_in[7];
    const float* W3   = (const float*)d_in[8];
    const float* b3   = (const float*)d_in[9];
    float* out = (float*)d_out;

    cudaFuncSetAttribute(fused_kernel, cudaFuncAttributeMaxDynamicSharedMemorySize, SMEM_BYTES);

    dim3 grid(CHUNKS, S_);
    fused_kernel<<<grid, THREADS, SMEM_BYTES>>>(obs, mu, Sig, perm, W1, b1, W2, b2, W3, b3, out);
}

// round 16
// speedup vs baseline: 1.7152x; 1.1855x over previous
#include <cuda_runtime.h>
#include <cstdint>

#define S_  16
#define T_  400
#define F_  16
#define SF_ 250
#define G_  4
#define H1  32
#define H2  16

#define THREADS  256
#define R_       4
#define CHUNKS   9
#define ROWS_S   (T_ * (SF_ + 1))                    // 100400
#define ROWS_CTA ((ROWS_S + CHUNKS - 1) / CHUNKS)    // 11156

// P-table: 1600 rows (rowid = g*400+t), 32 fp16 c-values (64 B) per row,
// 80-B stride -> 16B-chunk start-slot = (5t+q) mod 8, uniform.
#define P_STRIDE 80
#define P_BYTES  (G_ * T_ * P_STRIDE)                // 128000
#define OFF_W1   P_BYTES                              // f32 W1eff [j][c], 2048 B
#define OFF_W2H  (OFF_W1 + 2048)                      // fp16x2 W2 [i][jp], 1024 B
#define OFF_B1   (OFF_W2H + 1024)                     // f32 b1eff, 128 B
#define OFF_B2H  (OFF_B1 + 128)                       // fp16x2 b2, 32 B
#define OFF_W3   (OFF_B2H + 32)                       // f32 W3, 64 B
#define SMEM_BYTES (OFF_W3 + 64)

typedef unsigned long long ull;
typedef unsigned int u32;

__device__ __forceinline__ ull pk2(float a, float b) {
    ull r; asm("mov.b64 %0, {%1,%2};" : "=l"(r) : "f"(a), "f"(b)); return r;
}
__device__ __forceinline__ void upk(ull p, float& a, float& b) {
    asm("mov.b64 {%0,%1}, %2;" : "=f"(a), "=f"(b) : "l"(p));
}
__device__ __forceinline__ ull fma2(ull a, ull b, ull c) {
    ull d; asm("fma.rn.f32x2 %0, %1, %2, %3;" : "=l"(d) : "l"(a), "l"(b), "l"(c)); return d;
}
__device__ __forceinline__ u32 hadd2(u32 a, u32 b) {
    u32 d; asm("add.rn.f16x2 %0, %1, %2;" : "=r"(d) : "r"(a), "r"(b)); return d;
}
__device__ __forceinline__ u32 hmul2(u32 a, u32 b) {
    u32 d; asm("mul.rn.f16x2 %0, %1, %2;" : "=r"(d) : "r"(a), "r"(b)); return d;
}
__device__ __forceinline__ u32 hmax2(u32 a, u32 b) {
    u32 d; asm("max.f16x2 %0, %1, %2;" : "=r"(d) : "r"(a), "r"(b)); return d;
}
__device__ __forceinline__ u32 hfma2(u32 a, u32 b, u32 c) {
    u32 d; asm("fma.rn.f16x2 %0, %1, %2, %3;" : "=r"(d) : "r"(a), "r"(b), "r"(c)); return d;
}
__device__ __forceinline__ u32 prmt(u32 a, u32 sel) {
    u32 d; asm("prmt.b32 %0, %1, %1, %2;" : "=r"(d) : "r"(a), "r"(sel)); return d;
}
// pack two f32 into fp16x2 (x0 -> low half)
__device__ __forceinline__ u32 f2h2(float x0, float x1) {
    u32 r; asm("cvt.rn.f16x2.f32 %0, %1, %2;" : "=r"(r) : "f"(x1), "f"(x0)); return r;
}
// unpack fp16x2 -> two f32 (low half -> a)
__device__ __forceinline__ void h2f2(u32 h, float& a, float& b) {
    unsigned short lo = (unsigned short)(h & 0xFFFF);
    unsigned short hi = (unsigned short)(h >> 16);
    asm("cvt.f32.f16 %0, %1;" : "=f"(a) : "h"(lo));
    asm("cvt.f32.f16 %0, %1;" : "=f"(b) : "h"(hi));
}

struct RowIdx { int off[G_]; };   // byte offsets of P rows

__device__ __forceinline__ RowIdx load_idx(const int* __restrict__ perm, int s, int idx) {
    RowIdx r;
    int sfp = idx / T_;
    int t   = idx - sfp * T_;
    if (sfp == 0) {
        r.off[0] = t * P_STRIDE;
        r.off[1] = (T_ + t) * P_STRIDE;
        r.off[2] = (2 * T_ + t) * P_STRIDE;
        r.off[3] = (3 * T_ + t) * P_STRIDE;
    } else {
        int base = ((sfp - 1) * (G_ * S_) + s) * T_ + t;
        r.off[0] = perm[base] * P_STRIDE;
        r.off[1] = (T_ + perm[base + S_ * T_]) * P_STRIDE;
        r.off[2] = (2 * T_ + perm[base + 2 * S_ * T_]) * P_STRIDE;
        r.off[3] = (3 * T_ + perm[base + 3 * S_ * T_]) * P_STRIDE;
    }
    return r;
}

__global__ __launch_bounds__(THREADS, 1)
void fused_kernel(const float* __restrict__ obs,
                  const float* __restrict__ mu,
                  const float* __restrict__ Sig,
                  const int*   __restrict__ perm,
                  const float* __restrict__ W1,
                  const float* __restrict__ b1,
                  const float* __restrict__ W2,
                  const float* __restrict__ b2,
                  const float* __restrict__ W3,
                  const float* __restrict__ b3,
                  float* __restrict__ out) {
    extern __shared__ __align__(16) char sm[];
    float* sW1 = (float*)(sm + OFF_W1);   // [j][c] stride 32
    u32*   sW2h = (u32*)(sm + OFF_W2H);   // [i][jp] fp16x2
    float* sB1 = (float*)(sm + OFF_B1);
    u32*   sB2h = (u32*)(sm + OFF_B2H);   // 8 fp16x2
    float* sW3 = (float*)(sm + OFF_W3);

    const int s   = blockIdx.y;
    const int k   = blockIdx.x;
    const int tid = threadIdx.x;

    // ---- W1eff = Sigma^T W1 (normalize folded into layer 1) ----
    for (int m = tid; m < F_ * H1; m += THREADS) {
        int j = m >> 5, c = m & 31;
        float acc = 0.f;
        #pragma unroll
        for (int i = 0; i < F_; i++) acc += Sig[i * F_ + j] * W1[i * H1 + c];
        sW1[j * H1 + c] = acc;
    }
    // ---- b1eff = b1 - mu^T W1eff ----
    if (tid < H1) {
        int c = tid;
        float bacc = 0.f;
        #pragma unroll
        for (int j = 0; j < F_; j++) {
            float wj = 0.f;
            #pragma unroll
            for (int i = 0; i < F_; i++) wj += Sig[i * F_ + j] * W1[i * H1 + c];
            bacc += mu[j] * wj;
        }
        sB1[c] = b1[c] - bacc;
    }
    // ---- W2 -> fp16x2 [i][jp] ----
    for (int m = tid; m < H1 * (H2 / 2); m += THREADS) {
        int i = m >> 3, jp = m & 7;
        sW2h[i * 8 + jp] = f2h2(W2[i * H2 + 2 * jp], W2[i * H2 + 2 * jp + 1]);
    }
    if (tid < 8) sB2h[tid] = f2h2(b2[2 * tid], b2[2 * tid + 1]);
    if (tid < H2) sW3[tid] = W3[tid];
    __syncthreads();

    // ---- build fp16 P table (b1eff folded into g==0 rows) ----
    const float* obsS = obs + s * (T_ * F_);
    for (int it = tid; it < G_ * T_; it += THREADS) {
        int g = it / T_, t = it - g * T_;
        float4 x = *(const float4*)(obsS + t * F_ + g * 4);
        ull xx = pk2(x.x, x.x), xy = pk2(x.y, x.y);
        ull xz = pk2(x.z, x.z), xw = pk2(x.w, x.w);
        const char* wrow = (const char*)sW1 + g * 4 * 128;
        const ull* bp = (const ull*)sB1;
        u32 hp[16];
        #pragma unroll
        for (int cp = 0; cp < 16; cp++) {
            ull acc = (g == 0) ? bp[cp] : 0ULL;
            acc = fma2(xx, *(const ull*)(wrow + cp * 8), acc);
            acc = fma2(xy, *(const ull*)(wrow + 128 + cp * 8), acc);
            acc = fma2(xz, *(const ull*)(wrow + 256 + cp * 8), acc);
            acc = fma2(xw, *(const ull*)(wrow + 384 + cp * 8), acc);
            float a, b;
            upk(acc, a, b);
            hp[cp] = f2h2(a, b);
        }
        char* dst = sm + it * P_STRIDE;
        #pragma unroll
        for (int q = 0; q < 4; q++)
            *(uint4*)(dst + q * 16) = make_uint4(hp[4 * q], hp[4 * q + 1],
                                                 hp[4 * q + 2], hp[4 * q + 3]);
    }
    __syncthreads();

    const float b3v = b3[0];
    const int rowsBeg = k * ROWS_CTA;
    const int rowsEnd = (rowsBeg + ROWS_CTA < ROWS_S) ? rowsBeg + ROWS_CTA : ROWS_S;
    float* outS = out + s * ROWS_S;

    const u32 c001h = f2h2(0.01f, 0.01f);

    int idx0 = rowsBeg + tid;
    if (idx0 >= rowsEnd) return;

    RowIdx ra[R_];
    #pragma unroll
    for (int r = 0; r < R_; r++) {
        int id = idx0 + r * THREADS;
        ra[r] = load_idx(perm, s, id < rowsEnd ? id : rowsEnd - 1);
    }

    while (true) {
        const int curBase = idx0;
        RowIdx ci[R_];
        #pragma unroll
        for (int r = 0; r < R_; r++) ci[r] = ra[r];

        // ---- prefetch next iteration's perm indices ----
        idx0 += R_ * THREADS;
        const bool more = (idx0 < rowsEnd);
        if (more) {
            #pragma unroll
            for (int r = 0; r < R_; r++) {
                int id = idx0 + r * THREADS;
                ra[r] = load_idx(perm, s, id < rowsEnd ? id : rowsEnd - 1);
            }
        }

        // ---- layer 1: gather 4 fp16 P rows per row, HADD2 tree ----
        u32 h[R_][16];
        #pragma unroll
        for (int r = 0; r < R_; r++) {
            #pragma unroll
            for (int q = 0; q < 4; q++) {
                uint4 a = *(const uint4*)(sm + ci[r].off[0] + q * 16);
                uint4 b = *(const uint4*)(sm + ci[r].off[1] + q * 16);
                uint4 c = *(const uint4*)(sm + ci[r].off[2] + q * 16);
                uint4 d = *(const uint4*)(sm + ci[r].off[3] + q * 16);
                h[r][4 * q + 0] = hadd2(hadd2(a.x, b.x), hadd2(c.x, d.x));
                h[r][4 * q + 1] = hadd2(hadd2(a.y, b.y), hadd2(c.y, d.y));
                h[r][4 * q + 2] = hadd2(hadd2(a.z, b.z), hadd2(c.z, d.z));
                h[r][4 * q + 3] = hadd2(hadd2(a.w, b.w), hadd2(c.w, d.w));
            }
        }

        // ---- layer-2 accumulators: even-i into accE (init b2), odd-i into accO ----
        u32 accE[R_][8], accO[R_][8];
        #pragma unroll
        for (int r = 0; r < R_; r++)
            #pragma unroll
            for (int p = 0; p < 8; p++) { accE[r][p] = sB2h[p]; accO[r][p] = 0; }

        // ---- fp16 lrelu + HFMA2 layer 2 ----
        #pragma unroll
        for (int cp = 0; cp < 16; cp++) {
            uint4 we0 = *(const uint4*)(sW2h + (2 * cp) * 8);
            uint4 we1 = *(const uint4*)(sW2h + (2 * cp) * 8 + 4);
            uint4 wo0 = *(const uint4*)(sW2h + (2 * cp + 1) * 8);
            uint4 wo1 = *(const uint4*)(sW2h + (2 * cp + 1) * 8 + 4);
            #pragma unroll
            for (int r = 0; r < R_; r++) {
                u32 a = hmax2(h[r][cp], hmul2(h[r][cp], c001h));   // fp16 lrelu
                u32 ae = prmt(a, 0x1010);   // (a_even, a_even)
                u32 ao = prmt(a, 0x3232);   // (a_odd, a_odd)
                accE[r][0] = hfma2(ae, we0.x, accE[r][0]);
                accE[r][1] = hfma2(ae, we0.y, accE[r][1]);
                accE[r][2] = hfma2(ae, we0.z, accE[r][2]);
                accE[r][3] = hfma2(ae, we0.w, accE[r][3]);
                accE[r][4] = hfma2(ae, we1.x, accE[r][4]);
                accE[r][5] = hfma2(ae, we1.y, accE[r][5]);
                accE[r][6] = hfma2(ae, we1.z, accE[r][6]);
                accE[r][7] = hfma2(ae, we1.w, accE[r][7]);
                accO[r][0] = hfma2(ao, wo0.x, accO[r][0]);
                accO[r][1] = hfma2(ao, wo0.y, accO[r][1]);
                accO[r][2] = hfma2(ao, wo0.z, accO[r][2]);
                accO[r][3] = hfma2(ao, wo0.w, accO[r][3]);
                accO[r][4] = hfma2(ao, wo1.x, accO[r][4]);
                accO[r][5] = hfma2(ao, wo1.y, accO[r][5]);
                accO[r][6] = hfma2(ao, wo1.z, accO[r][6]);
                accO[r][7] = hfma2(ao, wo1.w, accO[r][7]);
            }
        }

        // ---- layer 3 (fp32) + sigmoid + guarded store ----
        const ull* w3p = (const ull*)sW3;
        #pragma unroll
        for (int r = 0; r < R_; r++) {
            ull zp = 0;
            #pragma unroll
            for (int p = 0; p < 8; p++) {
                u32 h2 = hadd2(accE[r][p], accO[r][p]);
                u32 lr = hmax2(h2, hmul2(h2, c001h));
                float fa, fb;
                h2f2(lr, fa, fb);
                zp = fma2(pk2(fa, fb), w3p[p], zp);
            }
            float z0, z1;
            upk(zp, z0, z1);
            float z = b3v + z0 + z1;
            int cid = curBase + r * THREADS;
            if (cid < rowsEnd) outS[cid] = 1.f / (1.f + __expf(-z));
        }

        if (!more) break;
    }
}

extern "C" void kernel_launch(void* const* d_in, const int* in_sizes, int n_in,
                              void* d_out, int out_size) {
    const float* obs  = (const float*)d_in[0];
    const float* mu   = (const float*)d_in[1];
    const float* Sig  = (const float*)d_in[2];
    const int*   perm = (const int*)d_in[3];
    const float* W1   = (const float*)d_in[4];
    const float* b1   = (const float*)d_in[5];
    const float* W2   = (const float*)d_in[6];
    const float* b2   = (const float*)d_in[7];
    const float* W3   = (const float*)d_in[8];
    const float* b3   = (const float*)d_in[9];
    float* out = (float*)d_out;

    cudaFuncSetAttribute(fused_kernel, cudaFuncAttributeMaxDynamicSharedMemorySize, SMEM_BYTES);

    dim3 grid(CHUNKS, S_);
    fused_kernel<<<grid, THREADS, SMEM_BYTES>>>(obs, mu, Sig, perm, W1, b1, W2, b2, W3, b3, out);
}